// round 4
// baseline (speedup 1.0000x reference)
#include <cuda_runtime.h>

#define QPB 8                 // quads (4-batch groups) per block
#define NTHREADS (QPB * 8)    // 8 threads per quad
#define SLOT 1112             // floats per quad slot; 1112 % 32 == 24 (bank spread over g)
#define BSTRIDE 268           // floats per batch inside slot; 268 % 32 == 12

typedef unsigned long long u64;

__device__ __forceinline__ u64 pk2(float a, float b) {
    u64 r; asm("mov.b64 %0,{%1,%2};" : "=l"(r) : "f"(a), "f"(b)); return r;
}
__device__ __forceinline__ u64 pk1(float a) { return pk2(a, a); }
__device__ __forceinline__ void up2(u64 v, float& a, float& b) {
    asm("mov.b64 {%0,%1},%2;" : "=f"(a), "=f"(b) : "l"(v));
}
__device__ __forceinline__ u64 fma2_(u64 a, u64 b, u64 c) {
    u64 d; asm("fma.rn.f32x2 %0,%1,%2,%3;" : "=l"(d) : "l"(a), "l"(b), "l"(c)); return d;
}
__device__ __forceinline__ u64 add2_(u64 a, u64 b) {
    u64 d; asm("add.rn.f32x2 %0,%1,%2;" : "=l"(d) : "l"(a), "l"(b)); return d;
}
__device__ __forceinline__ u64 mul2_(u64 a, u64 b) {
    u64 d; asm("mul.rn.f32x2 %0,%1,%2;" : "=l"(d) : "l"(a), "l"(b)); return d;
}
__device__ __forceinline__ float lrelu(float x) { return fmaxf(x, 0.01f * x); }

__global__ void __launch_bounds__(NTHREADS, 5)
gcn_kernel(const float* __restrict__ x,   const float* __restrict__ adj,
           const float* __restrict__ edge,
           const float* __restrict__ wb,  const float* __restrict__ bb,
           const float* __restrict__ w1,  const float* __restrict__ b1,
           const float* __restrict__ w2,  const float* __restrict__ b2,
           const float* __restrict__ wg,  const float* __restrict__ bg,
           const float* __restrict__ wf,  const float* __restrict__ bf,
           float* __restrict__ out)
{
    // Per-quad slot (SLOT floats), 4 batches per quad:
    //  Phase A (x stage, straight copy): batch b at b*BSTRIDE .. +263
    //  ty stash: 1072 + b*8 + v  (outside x region)
    //  Phase B aliases x region:
    //    FkT rows:  b*64  + k*8 + o          (0..255)   [xp aliases this later: b*8+o]
    //    S->q rows: 256 + b*64 + i*8 + v     (256..511)
    //    p rows:    512 + b*128 + w*16 + j   (512..1023)
    //    h2 rows:   512 + b*64  + u*8 + c    (512..767, p dead by then)
    __shared__ __align__(16) float s_u[QPB * SLOT];
    __shared__ __align__(16) float s_w1[32][16];
    __shared__ __align__(16) float s_wbT[32][8];
    __shared__ __align__(16) float s_w2[16][8];
    __shared__ __align__(16) float s_wg[8][8];
    __shared__ __align__(16) float s_bb[8];
    __shared__ __align__(16) float s_b1[16];
    __shared__ __align__(16) float s_b2[8];
    __shared__ float s_bg[8], s_wf[16], s_bf[2];

    const int tid = threadIdx.x;
    const int g = tid >> 3;
    const int v = tid & 7;
    const size_t quad = (size_t)blockIdx.x * QPB + g;
    const size_t b0 = quad * 4;

    // early L2 prefetch of adj/edge rows this thread will need mid-kernel
    #pragma unroll
    for (int b = 0; b < 4; b++) {
        asm volatile("prefetch.global.L2 [%0];" :: "l"(adj  + (b0 + b) * 64 + v * 8));
        asm volatile("prefetch.global.L2 [%0];" :: "l"(edge + (b0 + b) * 64 + v * 8));
    }

    for (int i = tid; i < 512; i += NTHREADS) ((float*)s_w1)[i] = w1[i];
    for (int i = tid; i < 256; i += NTHREADS) {
        int c = i >> 3, o = i & 7;
        s_wbT[c][o] = wb[o * 32 + c];
    }
    for (int i = tid; i < 128; i += NTHREADS) ((float*)s_w2)[i] = w2[i];
    if (tid < 64) ((float*)s_wg)[tid] = wg[tid];
    if (tid < 16) { s_b1[tid] = b1[tid]; s_wf[tid] = wf[tid]; }
    if (tid < 8)  { s_bb[tid] = bb[tid]; s_b2[tid] = b2[tid]; s_bg[tid] = bg[tid]; }
    if (tid < 2)  { s_bf[tid] = bf[tid]; }

    {   // straight float4 copy of the block's 32 batches of x
        const float4* xsrc = (const float4*)(x + (size_t)blockIdx.x * (QPB * 4 * 264));
        float4* dst4 = (float4*)s_u;
        #pragma unroll 1
        for (int i = tid; i < QPB * 4 * 66; i += NTHREADS) {
            int bl = i / 66;
            int j  = i - bl * 66;
            int qq = bl >> 2, bq = bl & 3;
            dst4[qq * (SLOT / 4) + bq * (BSTRIDE / 4) + j] = xsrc[i];
        }
    }
    __syncthreads();

    float* Xg = s_u + g * SLOT;

    // stash node types (region survives aliasing)
    #pragma unroll
    for (int b = 0; b < 4; b++) Xg[1072 + b * 8 + v] = Xg[b * BSTRIDE + v * 33];

    // ================= phase 1: Fk column v and p row v, 4 batches jointly
    u64 Fk[4][4], pa[4][8];
    #pragma unroll
    for (int b = 0; b < 4; b++) {
        #pragma unroll
        for (int i = 0; i < 4; i++) Fk[b][i] = 0ull;
        #pragma unroll
        for (int i = 0; i < 8; i++) pa[b][i] = 0ull;
    }
    const float* f0p = Xg + 0 * BSTRIDE + v * 33 + 1;
    const float* f1p = Xg + 1 * BSTRIDE + v * 33 + 1;
    const float* f2p = Xg + 2 * BSTRIDE + v * 33 + 1;
    const float* f3p = Xg + 3 * BSTRIDE + v * 33 + 1;
    #pragma unroll 2
    for (int c = 0; c < 32; c++) {
        u64 qv[4];
        qv[0] = pk1(f0p[c]); qv[1] = pk1(f1p[c]);
        qv[2] = pk1(f2p[c]); qv[3] = pk1(f3p[c]);
        const ulonglong2* w1r = (const ulonglong2*)s_w1[c];
        const ulonglong2* wbr = (const ulonglong2*)s_wbT[c];
        #pragma unroll
        for (int jj = 0; jj < 4; jj++) {
            ulonglong2 w = w1r[jj];
            #pragma unroll
            for (int b = 0; b < 4; b++) {
                pa[b][jj * 2]     = fma2_(qv[b], w.x, pa[b][jj * 2]);
                pa[b][jj * 2 + 1] = fma2_(qv[b], w.y, pa[b][jj * 2 + 1]);
            }
        }
        #pragma unroll
        for (int oo = 0; oo < 2; oo++) {
            ulonglong2 w = wbr[oo];
            #pragma unroll
            for (int b = 0; b < 4; b++) {
                Fk[b][oo * 2]     = fma2_(qv[b], w.x, Fk[b][oo * 2]);
                Fk[b][oo * 2 + 1] = fma2_(qv[b], w.y, Fk[b][oo * 2 + 1]);
            }
        }
    }
    #pragma unroll
    for (int i = 0; i < 4; i++) {
        u64 bbp = ((const u64*)s_bb)[i];
        #pragma unroll
        for (int b = 0; b < 4; b++) Fk[b][i] = add2_(Fk[b][i], bbp);
    }

    __syncwarp();   // feat reads done -> alias x region
    #pragma unroll
    for (int b = 0; b < 4; b++) {
        ulonglong2* d = (ulonglong2*)(Xg + b * 64 + v * 8);
        d[0] = make_ulonglong2(Fk[b][0], Fk[b][1]);
        d[1] = make_ulonglong2(Fk[b][2], Fk[b][3]);
        ulonglong2* dp = (ulonglong2*)(Xg + 512 + b * 128 + v * 16);
        dp[0] = make_ulonglong2(pa[b][0], pa[b][1]);
        dp[1] = make_ulonglong2(pa[b][2], pa[b][3]);
        dp[2] = make_ulonglong2(pa[b][4], pa[b][5]);
        dp[3] = make_ulonglong2(pa[b][6], pa[b][7]);
    }
    __syncwarp();

    // ================= M column v per batch, softmax over rows, write S
    #pragma unroll
    for (int b = 0; b < 4; b++) {
        float fks[8];
        #pragma unroll
        for (int i = 0; i < 4; i++) up2(Fk[b][i], fks[2 * i], fks[2 * i + 1]);
        u64 Mv[4] = {0ull, 0ull, 0ull, 0ull};
        #pragma unroll
        for (int k = 0; k < 8; k++) {
            ulonglong2 ra = *(const ulonglong2*)(Xg + b * 64 + k * 8);
            ulonglong2 rb = *(const ulonglong2*)(Xg + b * 64 + k * 8 + 4);
            u64 s = pk1(fks[k]);
            Mv[0] = fma2_(s, ra.x, Mv[0]);
            Mv[1] = fma2_(s, ra.y, Mv[1]);
            Mv[2] = fma2_(s, rb.x, Mv[2]);
            Mv[3] = fma2_(s, rb.y, Mv[3]);
        }
        float m[8];
        #pragma unroll
        for (int i = 0; i < 4; i++) up2(Mv[i], m[2 * i], m[2 * i + 1]);
        float mx = m[0];
        #pragma unroll
        for (int i = 1; i < 8; i++) mx = fmaxf(mx, m[i]);
        float se = 0.f;
        #pragma unroll
        for (int i = 0; i < 8; i++) { m[i] = __expf(m[i] - mx); se += m[i]; }
        float inv = 1.f / se;
        #pragma unroll
        for (int i = 0; i < 8; i++) Xg[256 + b * 64 + i * 8 + v] = m[i] * inv;
    }
    __syncwarp();

    // ================= W rows (4 batches) in registers
    float Wr[4][8];
    #pragma unroll
    for (int b = 0; b < 4; b++) {
        const float4* ap = (const float4*)(adj  + (b0 + b) * 64 + v * 8);
        const float4* ep = (const float4*)(edge + (b0 + b) * 64 + v * 8);
        float4 a0 = ap[0], a1 = ap[1], e0 = ep[0], e1 = ep[1];
        float4 S0 = *(const float4*)(Xg + 256 + b * 64 + v * 8);
        float4 S1 = *(const float4*)(Xg + 256 + b * 64 + v * 8 + 4);
        Wr[b][0] = a0.x * (S0.x + e0.x); Wr[b][1] = a0.y * (S0.y + e0.y);
        Wr[b][2] = a0.z * (S0.z + e0.z); Wr[b][3] = a0.w * (S0.w + e0.w);
        Wr[b][4] = a1.x * (S1.x + e1.x); Wr[b][5] = a1.y * (S1.y + e1.y);
        Wr[b][6] = a1.z * (S1.z + e1.z); Wr[b][7] = a1.w * (S1.w + e1.w);
    }
    __syncwarp();   // all S reads done before q overwrites that region

    // ================= h1 + q per batch half (lanes = channel pairs)
    #pragma unroll
    for (int bh = 0; bh < 2; bh++) {
        const int ba = 2 * bh, bc = 2 * bh + 1;
        u64 ha[2][8];
        #pragma unroll
        for (int i = 0; i < 8; i++) { ha[0][i] = 0ull; ha[1][i] = 0ull; }
        #pragma unroll
        for (int w = 0; w < 8; w++) {
            u64 w0 = pk1(Wr[ba][w]), w1p = pk1(Wr[bc][w]);
            const ulonglong2* pr0 = (const ulonglong2*)(Xg + 512 + ba * 128 + w * 16);
            const ulonglong2* pr1 = (const ulonglong2*)(Xg + 512 + bc * 128 + w * 16);
            #pragma unroll
            for (int jj = 0; jj < 4; jj++) {
                ulonglong2 r0 = pr0[jj], r1 = pr1[jj];
                ha[0][jj * 2]     = fma2_(w0, r0.x, ha[0][jj * 2]);
                ha[0][jj * 2 + 1] = fma2_(w0, r0.y, ha[0][jj * 2 + 1]);
                ha[1][jj * 2]     = fma2_(w1p, r1.x, ha[1][jj * 2]);
                ha[1][jj * 2 + 1] = fma2_(w1p, r1.y, ha[1][jj * 2 + 1]);
            }
        }
        float hs[2][16];
        #pragma unroll
        for (int i = 0; i < 8; i++) {
            u64 b1p = ((const u64*)s_b1)[i];
            u64 t0 = add2_(ha[0][i], b1p), t1 = add2_(ha[1][i], b1p);
            up2(t0, hs[0][2 * i], hs[0][2 * i + 1]);
            up2(t1, hs[1][2 * i], hs[1][2 * i + 1]);
        }
        #pragma unroll
        for (int i = 0; i < 16; i++) { hs[0][i] = lrelu(hs[0][i]); hs[1][i] = lrelu(hs[1][i]); }

        u64 qa[2][4];
        #pragma unroll
        for (int i = 0; i < 4; i++) { qa[0][i] = 0ull; qa[1][i] = 0ull; }
        #pragma unroll
        for (int j = 0; j < 16; j++) {
            const ulonglong2* w2r = (const ulonglong2*)s_w2[j];
            ulonglong2 wA = w2r[0], wB = w2r[1];
            u64 hj0 = pk1(hs[0][j]), hj1 = pk1(hs[1][j]);
            qa[0][0] = fma2_(hj0, wA.x, qa[0][0]);
            qa[0][1] = fma2_(hj0, wA.y, qa[0][1]);
            qa[0][2] = fma2_(hj0, wB.x, qa[0][2]);
            qa[0][3] = fma2_(hj0, wB.y, qa[0][3]);
            qa[1][0] = fma2_(hj1, wA.x, qa[1][0]);
            qa[1][1] = fma2_(hj1, wA.y, qa[1][1]);
            qa[1][2] = fma2_(hj1, wB.x, qa[1][2]);
            qa[1][3] = fma2_(hj1, wB.y, qa[1][3]);
        }
        ulonglong2* dq0 = (ulonglong2*)(Xg + 256 + ba * 64 + v * 8);
        dq0[0] = make_ulonglong2(qa[0][0], qa[0][1]);
        dq0[1] = make_ulonglong2(qa[0][2], qa[0][3]);
        ulonglong2* dq1 = (ulonglong2*)(Xg + 256 + bc * 64 + v * 8);
        dq1[0] = make_ulonglong2(qa[1][0], qa[1][1]);
        dq1[1] = make_ulonglong2(qa[1][2], qa[1][3]);
    }
    __syncwarp();

    // ================= h2 per batch half, write h2 rows (p region dead)
    #pragma unroll
    for (int bh = 0; bh < 2; bh++) {
        const int ba = 2 * bh, bc = 2 * bh + 1;
        u64 h2a[2][4];
        #pragma unroll
        for (int i = 0; i < 4; i++) { h2a[0][i] = 0ull; h2a[1][i] = 0ull; }
        #pragma unroll
        for (int w = 0; w < 8; w++) {
            u64 w0 = pk1(Wr[ba][w]), w1p = pk1(Wr[bc][w]);
            ulonglong2 r0a = *(const ulonglong2*)(Xg + 256 + ba * 64 + w * 8);
            ulonglong2 r0b = *(const ulonglong2*)(Xg + 256 + ba * 64 + w * 8 + 4);
            ulonglong2 r1a = *(const ulonglong2*)(Xg + 256 + bc * 64 + w * 8);
            ulonglong2 r1b = *(const ulonglong2*)(Xg + 256 + bc * 64 + w * 8 + 4);
            h2a[0][0] = fma2_(w0, r0a.x, h2a[0][0]);
            h2a[0][1] = fma2_(w0, r0a.y, h2a[0][1]);
            h2a[0][2] = fma2_(w0, r0b.x, h2a[0][2]);
            h2a[0][3] = fma2_(w0, r0b.y, h2a[0][3]);
            h2a[1][0] = fma2_(w1p, r1a.x, h2a[1][0]);
            h2a[1][1] = fma2_(w1p, r1a.y, h2a[1][1]);
            h2a[1][2] = fma2_(w1p, r1b.x, h2a[1][2]);
            h2a[1][3] = fma2_(w1p, r1b.y, h2a[1][3]);
        }
        #pragma unroll
        for (int hb = 0; hb < 2; hb++) {
            int b = 2 * bh + hb;
            u64 t0 = add2_(h2a[hb][0], ((const u64*)s_b2)[0]);
            u64 t1 = add2_(h2a[hb][1], ((const u64*)s_b2)[1]);
            u64 t2 = add2_(h2a[hb][2], ((const u64*)s_b2)[2]);
            u64 t3 = add2_(h2a[hb][3], ((const u64*)s_b2)[3]);
            float e0, e1, e2, e3, e4, e5, e6, e7;
            up2(t0, e0, e1); up2(t1, e2, e3); up2(t2, e4, e5); up2(t3, e6, e7);
            ulonglong2* dst = (ulonglong2*)(Xg + 512 + b * 64 + v * 8);
            dst[0] = make_ulonglong2(pk2(lrelu(e0), lrelu(e1)), pk2(lrelu(e2), lrelu(e3)));
            dst[1] = make_ulonglong2(pk2(lrelu(e4), lrelu(e5)), pk2(lrelu(e6), lrelu(e7)));
        }
    }
    __syncwarp();

    // ================= attention pooling per batch: thread v = channel o
    {
        const ulonglong2* wgr = (const ulonglong2*)s_wg[v];
        ulonglong2 wgA = wgr[0], wgB = wgr[1];
        const float bgv = s_bg[v];
        #pragma unroll
        for (int b = 0; b < 4; b++) {
            float d[8], ho[8], tyu[8];
            #pragma unroll
            for (int u = 0; u < 8; u++) {
                ulonglong2 ra = *(const ulonglong2*)(Xg + 512 + b * 64 + u * 8);
                ulonglong2 rb = *(const ulonglong2*)(Xg + 512 + b * 64 + u * 8 + 4);
                u64 acc = mul2_(wgA.x, ra.x);
                acc = fma2_(wgA.y, ra.y, acc);
                acc = fma2_(wgB.x, rb.x, acc);
                acc = fma2_(wgB.y, rb.y, acc);
                float lo, hi; up2(acc, lo, hi);
                d[u] = lo + hi;
                ho[u]  = Xg[512 + b * 64 + u * 8 + v];
                tyu[u] = Xg[1072 + b * 8 + u];
            }
            float xp = 0.f;
            #pragma unroll
            for (int t = 0; t < 2; t++) {
                float tf = (float)t;
                float L[8], hm[8];
                float mx = -1e30f;
                #pragma unroll
                for (int u = 0; u < 8; u++) {
                    float ma = (tyu[u] == tf) ? 1.f : 0.f;
                    L[u] = ma * d[u] + bgv;
                    hm[u] = ma * ho[u];
                    mx = fmaxf(mx, L[u]);
                }
                float se = 0.f, nu = 0.f;
                #pragma unroll
                for (int u = 0; u < 8; u++) {
                    float e = __expf(L[u] - mx);
                    se += e; nu += e * hm[u];
                }
                xp += nu / se;
            }
            Xg[b * 8 + v] = 0.5f * xp;   // xp aliases dead FkT region
        }
    }
    __syncwarp();

    // ================= final linear: thread v -> (batch v>>1, class v&1)
    {
        const int bsel = v >> 1, cls = v & 1;
        float o = s_bf[cls];
        #pragma unroll
        for (int c = 0; c < 8; c++) o += Xg[bsel * 8 + c] * s_wf[cls * 8 + c];
        out[(b0 + bsel) * 2 + cls] = o;
    }
}

extern "C" void kernel_launch(void* const* d_in, const int* in_sizes, int n_in,
                              void* d_out, int out_size)
{
    const float* x    = (const float*)d_in[0];
    const float* adj  = (const float*)d_in[1];
    const float* edge = (const float*)d_in[2];
    const float* wb = (const float*)d_in[5];
    const float* bb = (const float*)d_in[6];
    const float* w1 = (const float*)d_in[7];
    const float* b1 = (const float*)d_in[8];
    const float* w2 = (const float*)d_in[9];
    const float* b2 = (const float*)d_in[10];
    const float* wg = (const float*)d_in[11];
    const float* bg = (const float*)d_in[12];
    const float* wf = (const float*)d_in[13];
    const float* bf = (const float*)d_in[14];

    const int B = in_sizes[0] / 264;
    const int grid = B / (4 * QPB);      // 4 batches per quad, 8 quads per block
    gcn_kernel<<<grid, NTHREADS>>>(x, adj, edge, wb, bb, w1, b1, w2, b2,
                                   wg, bg, wf, bf, (float*)d_out);
}

// round 5
// speedup vs baseline: 2.2811x; 2.2811x over previous
#include <cuda_runtime.h>

#define PAIRS_PER_BLOCK 8
#define NTHREADS (PAIRS_PER_BLOCK * 8)
#define SLOT 552            // floats per pair slot; 552 % 32 == 8
#define BSTRIDE 268         // floats per batch inside slot; 268 % 32 == 12

typedef unsigned long long u64;

struct WPack {
    float w1[32][16];   // 512
    float wbT[32][8];   // 256 (transposed by prep kernel)
    float w2[16][8];    // 128
    float wg[8][8];     // 64
    float bb[8];
    float b1[16];
    float b2[8];
    float bg[8];
    float wf[16];
    float bf[2];
};

__device__ WPack g_pack;          // scratch (device global, no alloc)
__constant__ WPack c_w;           // filled via D2D memcpy each launch

__global__ void prep_kernel(const float* __restrict__ wb, const float* __restrict__ bb,
                            const float* __restrict__ w1, const float* __restrict__ b1,
                            const float* __restrict__ w2, const float* __restrict__ b2,
                            const float* __restrict__ wg, const float* __restrict__ bg,
                            const float* __restrict__ wf, const float* __restrict__ bf)
{
    int t = threadIdx.x;
    for (int i = t; i < 512; i += blockDim.x) ((float*)g_pack.w1)[i] = w1[i];
    for (int i = t; i < 256; i += blockDim.x) {
        int c = i >> 3, o = i & 7;
        g_pack.wbT[c][o] = wb[o * 32 + c];
    }
    for (int i = t; i < 128; i += blockDim.x) ((float*)g_pack.w2)[i] = w2[i];
    if (t < 64) ((float*)g_pack.wg)[t] = wg[t];
    if (t < 16) { g_pack.b1[t] = b1[t]; g_pack.wf[t] = wf[t]; }
    if (t < 8)  { g_pack.bb[t] = bb[t]; g_pack.b2[t] = b2[t]; g_pack.bg[t] = bg[t]; }
    if (t < 2)  { g_pack.bf[t] = bf[t]; }
}

__device__ __forceinline__ u64 pk2(float a, float b) {
    u64 r; asm("mov.b64 %0,{%1,%2};" : "=l"(r) : "f"(a), "f"(b)); return r;
}
__device__ __forceinline__ u64 pk1(float a) { return pk2(a, a); }
__device__ __forceinline__ void up2(u64 v, float& a, float& b) {
    asm("mov.b64 {%0,%1},%2;" : "=f"(a), "=f"(b) : "l"(v));
}
__device__ __forceinline__ u64 fma2_(u64 a, u64 b, u64 c) {
    u64 d; asm("fma.rn.f32x2 %0,%1,%2,%3;" : "=l"(d) : "l"(a), "l"(b), "l"(c)); return d;
}
__device__ __forceinline__ u64 add2_(u64 a, u64 b) {
    u64 d; asm("add.rn.f32x2 %0,%1,%2;" : "=l"(d) : "l"(a), "l"(b)); return d;
}
__device__ __forceinline__ u64 mul2_(u64 a, u64 b) {
    u64 d; asm("mul.rn.f32x2 %0,%1,%2;" : "=l"(d) : "l"(a), "l"(b)); return d;
}
__device__ __forceinline__ float lrelu(float x) { return fmaxf(x, 0.01f * x); }

__global__ void __launch_bounds__(NTHREADS, 12)
gcn_kernel(const float* __restrict__ x,   const float* __restrict__ adj,
           const float* __restrict__ edge,
           float* __restrict__ out)
{
    // Per-pair slot (SLOT floats):
    //  Phase A (x stage): batch bb at bb*BSTRIDE .. +263
    //  ty stash: 536 + bb*8 + v
    //  Phase B aliases x region: FkT 0..127, S->q 128..255, p->h2 256..511, xp 512..527
    __shared__ __align__(16) float s_u[PAIRS_PER_BLOCK * SLOT];

    const int tid = threadIdx.x;

    {   // straight float4 copy: x tile -> per-batch regions
        const float4* xsrc = (const float4*)(x + (size_t)blockIdx.x * (PAIRS_PER_BLOCK * 2 * 264));
        float4* dst4 = (float4*)s_u;
        #pragma unroll 1
        for (int i = tid; i < PAIRS_PER_BLOCK * 2 * 66; i += NTHREADS) {
            int bl = i / 66;
            int j  = i - bl * 66;
            int pr = bl >> 1, bbx = bl & 1;
            dst4[pr * (SLOT / 4) + bbx * (BSTRIDE / 4) + j] = xsrc[i];
        }
    }
    __syncthreads();

    const int g = tid >> 3;
    const int v = tid & 7;
    const size_t pair = (size_t)blockIdx.x * PAIRS_PER_BLOCK + g;
    const size_t b0 = pair * 2;
    float* Xg = s_u + g * SLOT;

    // stash node types outside the aliased region
    Xg[536 + 0 * 8 + v] = Xg[0 * BSTRIDE + v * 33];
    Xg[536 + 1 * 8 + v] = Xg[1 * BSTRIDE + v * 33];

    // ================= phase 1: Fk column v (o-paired), p row v (j-paired)
    u64 Fk[2][4], p[2][8];
    #pragma unroll
    for (int i = 0; i < 4; i++) { Fk[0][i] = 0ull; Fk[1][i] = 0ull; }
    #pragma unroll
    for (int i = 0; i < 8; i++) { p[0][i] = 0ull; p[1][i] = 0ull; }

    const float* f0 = Xg + 0 * BSTRIDE + v * 33 + 1;
    const float* f1 = Xg + 1 * BSTRIDE + v * 33 + 1;
    #pragma unroll 8
    for (int c = 0; c < 32; c++) {
        u64 q0 = pk1(f0[c]), q1 = pk1(f1[c]);
        const ulonglong2* w1r = (const ulonglong2*)c_w.w1[c];
        const ulonglong2* wbr = (const ulonglong2*)c_w.wbT[c];
        #pragma unroll
        for (int jj = 0; jj < 4; jj++) {
            ulonglong2 w = w1r[jj];
            p[0][jj * 2]     = fma2_(q0, w.x, p[0][jj * 2]);
            p[0][jj * 2 + 1] = fma2_(q0, w.y, p[0][jj * 2 + 1]);
            p[1][jj * 2]     = fma2_(q1, w.x, p[1][jj * 2]);
            p[1][jj * 2 + 1] = fma2_(q1, w.y, p[1][jj * 2 + 1]);
        }
        #pragma unroll
        for (int oo = 0; oo < 2; oo++) {
            ulonglong2 w = wbr[oo];
            Fk[0][oo * 2]     = fma2_(q0, w.x, Fk[0][oo * 2]);
            Fk[0][oo * 2 + 1] = fma2_(q0, w.y, Fk[0][oo * 2 + 1]);
            Fk[1][oo * 2]     = fma2_(q1, w.x, Fk[1][oo * 2]);
            Fk[1][oo * 2 + 1] = fma2_(q1, w.y, Fk[1][oo * 2 + 1]);
        }
    }
    #pragma unroll
    for (int i = 0; i < 4; i++) {
        u64 bbp = ((const u64*)c_w.bb)[i];
        Fk[0][i] = add2_(Fk[0][i], bbp);
        Fk[1][i] = add2_(Fk[1][i], bbp);
    }

    __syncwarp();   // feat reads done -> alias x region
    {
        u64* d0 = (u64*)Xg + v * 4;
        u64* d1 = (u64*)Xg + 32 + v * 4;
        #pragma unroll
        for (int i = 0; i < 4; i++) { d0[i] = Fk[0][i]; d1[i] = Fk[1][i]; }
        u64* p0 = (u64*)(Xg + 256) + v * 8;
        u64* p1 = (u64*)(Xg + 256) + 64 + v * 8;
        #pragma unroll
        for (int i = 0; i < 8; i++) { p0[i] = p[0][i]; p1[i] = p[1][i]; }
    }
    __syncwarp();

    // ================= M column v, softmax over rows, write S rows
    {
        float fks[2][8];
        #pragma unroll
        for (int i = 0; i < 4; i++) {
            up2(Fk[0][i], fks[0][2 * i], fks[0][2 * i + 1]);
            up2(Fk[1][i], fks[1][2 * i], fks[1][2 * i + 1]);
        }
        u64 Mv[2][4];
        #pragma unroll
        for (int i = 0; i < 4; i++) { Mv[0][i] = 0ull; Mv[1][i] = 0ull; }
        #pragma unroll
        for (int k = 0; k < 8; k++) {
            ulonglong2 r0a = *(const ulonglong2*)(Xg + k * 8);
            ulonglong2 r0b = *(const ulonglong2*)(Xg + k * 8 + 4);
            ulonglong2 r1a = *(const ulonglong2*)(Xg + 64 + k * 8);
            ulonglong2 r1b = *(const ulonglong2*)(Xg + 64 + k * 8 + 4);
            u64 s0 = pk1(fks[0][k]), s1 = pk1(fks[1][k]);
            Mv[0][0] = fma2_(s0, r0a.x, Mv[0][0]);
            Mv[0][1] = fma2_(s0, r0a.y, Mv[0][1]);
            Mv[0][2] = fma2_(s0, r0b.x, Mv[0][2]);
            Mv[0][3] = fma2_(s0, r0b.y, Mv[0][3]);
            Mv[1][0] = fma2_(s1, r1a.x, Mv[1][0]);
            Mv[1][1] = fma2_(s1, r1a.y, Mv[1][1]);
            Mv[1][2] = fma2_(s1, r1b.x, Mv[1][2]);
            Mv[1][3] = fma2_(s1, r1b.y, Mv[1][3]);
        }
        #pragma unroll
        for (int b = 0; b < 2; b++) {
            float m[8];
            #pragma unroll
            for (int i = 0; i < 4; i++) up2(Mv[b][i], m[2 * i], m[2 * i + 1]);
            float mx = m[0];
            #pragma unroll
            for (int i = 1; i < 8; i++) mx = fmaxf(mx, m[i]);
            float se = 0.f;
            #pragma unroll
            for (int i = 0; i < 8; i++) { m[i] = __expf(m[i] - mx); se += m[i]; }
            float inv = 1.f / se;
            #pragma unroll
            for (int i = 0; i < 8; i++) Xg[128 + b * 64 + i * 8 + v] = m[i] * inv;
        }
    }
    __syncwarp();

    // ================= W row v in registers
    float Wr[2][8];
    #pragma unroll
    for (int b = 0; b < 2; b++) {
        const float4* ap = (const float4*)(adj  + (b0 + b) * 64 + v * 8);
        const float4* ep = (const float4*)(edge + (b0 + b) * 64 + v * 8);
        float4 a0 = ap[0], a1 = ap[1], e0 = ep[0], e1 = ep[1];
        float4 S0 = *(const float4*)(Xg + 128 + b * 64 + v * 8);
        float4 S1 = *(const float4*)(Xg + 128 + b * 64 + v * 8 + 4);
        Wr[b][0] = a0.x * (S0.x + e0.x); Wr[b][1] = a0.y * (S0.y + e0.y);
        Wr[b][2] = a0.z * (S0.z + e0.z); Wr[b][3] = a0.w * (S0.w + e0.w);
        Wr[b][4] = a1.x * (S1.x + e1.x); Wr[b][5] = a1.y * (S1.y + e1.y);
        Wr[b][6] = a1.z * (S1.z + e1.z); Wr[b][7] = a1.w * (S1.w + e1.w);
    }

    // ================= h1 row v (j-paired)
    u64 h[2][8];
    #pragma unroll
    for (int i = 0; i < 8; i++) { h[0][i] = 0ull; h[1][i] = 0ull; }
    #pragma unroll
    for (int w = 0; w < 8; w++) {
        u64 w0 = pk1(Wr[0][w]), w1p = pk1(Wr[1][w]);
        const ulonglong2* pr0 = (const ulonglong2*)(Xg + 256 + w * 16);
        const ulonglong2* pr1 = (const ulonglong2*)(Xg + 256 + 128 + w * 16);
        #pragma unroll
        for (int jj = 0; jj < 4; jj++) {
            ulonglong2 r0 = pr0[jj], r1 = pr1[jj];
            h[0][jj * 2]     = fma2_(w0, r0.x, h[0][jj * 2]);
            h[0][jj * 2 + 1] = fma2_(w0, r0.y, h[0][jj * 2 + 1]);
            h[1][jj * 2]     = fma2_(w1p, r1.x, h[1][jj * 2]);
            h[1][jj * 2 + 1] = fma2_(w1p, r1.y, h[1][jj * 2 + 1]);
        }
    }
    float hs[2][16];
    #pragma unroll
    for (int i = 0; i < 8; i++) {
        u64 b1p = ((const u64*)c_w.b1)[i];
        u64 t0 = add2_(h[0][i], b1p), t1 = add2_(h[1][i], b1p);
        up2(t0, hs[0][2 * i], hs[0][2 * i + 1]);
        up2(t1, hs[1][2 * i], hs[1][2 * i + 1]);
    }
    #pragma unroll
    for (int i = 0; i < 16; i++) { hs[0][i] = lrelu(hs[0][i]); hs[1][i] = lrelu(hs[1][i]); }

    // ================= q row v (k-paired)
    u64 qa[2][4];
    #pragma unroll
    for (int i = 0; i < 4; i++) { qa[0][i] = 0ull; qa[1][i] = 0ull; }
    #pragma unroll
    for (int j = 0; j < 16; j++) {
        const ulonglong2* w2r = (const ulonglong2*)c_w.w2[j];
        ulonglong2 wA = w2r[0], wB = w2r[1];
        u64 hj0 = pk1(hs[0][j]), hj1 = pk1(hs[1][j]);
        qa[0][0] = fma2_(hj0, wA.x, qa[0][0]);
        qa[0][1] = fma2_(hj0, wA.y, qa[0][1]);
        qa[0][2] = fma2_(hj0, wB.x, qa[0][2]);
        qa[0][3] = fma2_(hj0, wB.y, qa[0][3]);
        qa[1][0] = fma2_(hj1, wA.x, qa[1][0]);
        qa[1][1] = fma2_(hj1, wA.y, qa[1][1]);
        qa[1][2] = fma2_(hj1, wB.x, qa[1][2]);
        qa[1][3] = fma2_(hj1, wB.y, qa[1][3]);
    }
    __syncwarp();   // everyone done reading S before q overwrites it
    {
        u64* d0 = (u64*)(Xg + 128) + v * 4;
        u64* d1 = (u64*)(Xg + 128) + 32 + v * 4;
        #pragma unroll
        for (int i = 0; i < 4; i++) { d0[i] = qa[0][i]; d1[i] = qa[1][i]; }
    }
    __syncwarp();

    // ================= h2 row v (k-paired), write h2 rows
    {
        u64 h2a[2][4];
        #pragma unroll
        for (int i = 0; i < 4; i++) { h2a[0][i] = 0ull; h2a[1][i] = 0ull; }
        #pragma unroll
        for (int w = 0; w < 8; w++) {
            u64 w0 = pk1(Wr[0][w]), w1p = pk1(Wr[1][w]);
            ulonglong2 r0a = *(const ulonglong2*)(Xg + 128 + w * 8);
            ulonglong2 r0b = *(const ulonglong2*)(Xg + 128 + w * 8 + 4);
            ulonglong2 r1a = *(const ulonglong2*)(Xg + 128 + 64 + w * 8);
            ulonglong2 r1b = *(const ulonglong2*)(Xg + 128 + 64 + w * 8 + 4);
            h2a[0][0] = fma2_(w0, r0a.x, h2a[0][0]);
            h2a[0][1] = fma2_(w0, r0a.y, h2a[0][1]);
            h2a[0][2] = fma2_(w0, r0b.x, h2a[0][2]);
            h2a[0][3] = fma2_(w0, r0b.y, h2a[0][3]);
            h2a[1][0] = fma2_(w1p, r1a.x, h2a[1][0]);
            h2a[1][1] = fma2_(w1p, r1a.y, h2a[1][1]);
            h2a[1][2] = fma2_(w1p, r1b.x, h2a[1][2]);
            h2a[1][3] = fma2_(w1p, r1b.y, h2a[1][3]);
        }
        __syncwarp();
        #pragma unroll
        for (int b = 0; b < 2; b++) {
            u64* dst = (u64*)(Xg + 256) + b * 32 + v * 4;
            #pragma unroll
            for (int i = 0; i < 4; i++) {
                u64 t = add2_(h2a[b][i], ((const u64*)c_w.b2)[i]);
                float lo, hi; up2(t, lo, hi);
                dst[i] = pk2(lrelu(lo), lrelu(hi));
            }
        }
    }
    __syncwarp();

    // ================= attention pooling: thread v = output channel o
    {
        const ulonglong2* wgr = (const ulonglong2*)c_w.wg[v];
        ulonglong2 wgA = wgr[0], wgB = wgr[1];
        float d[2][8], ho[2][8], tyu[2][8];
        #pragma unroll
        for (int u = 0; u < 8; u++) {
            #pragma unroll
            for (int b = 0; b < 2; b++) {
                ulonglong2 ra = *(const ulonglong2*)(Xg + 256 + b * 64 + u * 8);
                ulonglong2 rb = *(const ulonglong2*)(Xg + 256 + b * 64 + u * 8 + 4);
                u64 acc = mul2_(wgA.x, ra.x);
                acc = fma2_(wgA.y, ra.y, acc);
                acc = fma2_(wgB.x, rb.x, acc);
                acc = fma2_(wgB.y, rb.y, acc);
                float lo, hi; up2(acc, lo, hi);
                d[b][u] = lo + hi;
                ho[b][u]  = Xg[256 + b * 64 + u * 8 + v];
                tyu[b][u] = Xg[536 + b * 8 + u];
            }
        }
        const float bgv = c_w.bg[v];
        #pragma unroll
        for (int b = 0; b < 2; b++) {
            float xp = 0.f;
            #pragma unroll
            for (int t = 0; t < 2; t++) {
                float tf = (float)t;
                float L[8], hm[8];
                float mx = -1e30f;
                #pragma unroll
                for (int u = 0; u < 8; u++) {
                    float ma = (tyu[b][u] == tf) ? 1.f : 0.f;
                    L[u] = ma * d[b][u] + bgv;
                    hm[u] = ma * ho[b][u];
                    mx = fmaxf(mx, L[u]);
                }
                float se = 0.f, nu = 0.f;
                #pragma unroll
                for (int u = 0; u < 8; u++) {
                    float e = __expf(L[u] - mx);
                    se += e; nu += e * hm[u];
                }
                xp += nu / se;
            }
            Xg[512 + b * 8 + v] = 0.5f * xp;
        }
    }
    __syncwarp();

    if (v < 2) {
        #pragma unroll
        for (int b = 0; b < 2; b++) {
            float o = c_w.bf[v];
            #pragma unroll
            for (int c = 0; c < 8; c++) o += Xg[512 + b * 8 + c] * c_w.wf[v * 8 + c];
            out[(b0 + b) * 2 + v] = o;
        }
    }
}

extern "C" void kernel_launch(void* const* d_in, const int* in_sizes, int n_in,
                              void* d_out, int out_size)
{
    const float* x    = (const float*)d_in[0];
    const float* adj  = (const float*)d_in[1];
    const float* edge = (const float*)d_in[2];
    const float* wb = (const float*)d_in[5];
    const float* bb = (const float*)d_in[6];
    const float* w1 = (const float*)d_in[7];
    const float* b1 = (const float*)d_in[8];
    const float* w2 = (const float*)d_in[9];
    const float* b2 = (const float*)d_in[10];
    const float* wg = (const float*)d_in[11];
    const float* bg = (const float*)d_in[12];
    const float* wf = (const float*)d_in[13];
    const float* bf = (const float*)d_in[14];

    // 1) pack + transpose weights into device scratch
    prep_kernel<<<1, 256>>>(wb, bb, w1, b1, w2, b2, wg, bg, wf, bf);

    // 2) D2D copy scratch -> constant bank (graph-capturable memcpy node)
    void* packAddr = nullptr;
    cudaGetSymbolAddress(&packAddr, g_pack);
    cudaMemcpyToSymbolAsync(c_w, packAddr, sizeof(WPack), 0, cudaMemcpyDeviceToDevice);

    // 3) main kernel
    const int B = in_sizes[0] / 264;
    const int grid = B / (2 * PAIRS_PER_BLOCK);
    gcn_kernel<<<grid, NTHREADS>>>(x, adj, edge, (float*)d_out);
}